// round 15
// baseline (speedup 1.0000x reference)
#include <cuda_runtime.h>
#include <cuda_fp16.h>
#include <cstdint>

#define NUM_TOKENS 131072
#define NUM_EXPERTS 256
#define TOPK 8
#define LOG2E 1.4426950408889634f

__device__ __forceinline__ float ex2(float x) {
    float y; asm("ex2.approx.ftz.f32 %0, %1;" : "=f"(y) : "f"(x)); return y;
}
__device__ __forceinline__ float lg2(float x) {
    float y; asm("lg2.approx.ftz.f32 %0, %1;" : "=f"(y) : "f"(x)); return y;
}

__global__ void __launch_bounds__(256, 6)
moe_topk_softmax_kernel(const float* __restrict__ gating,
                        float* __restrict__ out) {
    // Packed survivors: hi 32 = raw f32 bits of value, lo 32 = expert index.
    __shared__ __align__(16) unsigned long long sk[8][72];
    __shared__ __align__(16) __half2 sh[8][16];  // fp16-packed survivor values, slots 0..31
    const unsigned FULL = 0xffffffffu;
    const int wib  = threadIdx.x >> 5;
    const int lane = threadIdx.x & 31;
    const int warp = blockIdx.x * 8 + wib;
    const unsigned long long PAD = ((unsigned long long)0xff800000u << 32);  // -inf, idx 0
    const float NEG_INF = __int_as_float(0xff800000);

    // Coalesced row load: 64 float4 per row
    const float4* row = reinterpret_cast<const float4*>(gating + (size_t)warp * NUM_EXPERTS);
    float4 A = __ldg(&row[lane]);
    float4 B = __ldg(&row[lane + 32]);
    float v[8] = {A.x, A.y, A.z, A.w, B.x, B.y, B.z, B.w};

    // Per-lane max
    float lm = v[0];
#pragma unroll
    for (int j = 1; j < 8; j++) lm = fmaxf(lm, v[j]);

    // thr = min of the 8 quad maxima (8 disjoint 32-elem groups => thr <= t8, and
    // all 8 quad maxima >= thr => S >= 8). rmax = row max.
    float qm = fmaxf(lm, __shfl_xor_sync(FULL, lm, 1));
    qm = fmaxf(qm, __shfl_xor_sync(FULL, qm, 2));
    float thr = qm, rmax = qm;
#pragma unroll
    for (int o = 4; o < 32; o <<= 1) {
        thr  = fminf(thr,  __shfl_xor_sync(FULL, thr,  o));
        rmax = fmaxf(rmax, __shfl_xor_sync(FULL, rmax, o));
    }

    // ---- Softmax denominator early; fold into exponent offset ----
    const float rm2 = rmax * LOG2E;
    float sm = 0.f;
#pragma unroll
    for (int j = 0; j < 8; j++) sm += ex2(fmaf(v[j], LOG2E, -rm2));
#pragma unroll
    for (int o = 1; o < 32; o <<= 1) sm += __shfl_xor_sync(FULL, sm, o);
    const float woff = -rm2 - lg2(sm);   // weight = ex2(fma(v, LOG2E, woff))

    // ---- Flag mask + exclusive prefix scan of survivor counts ----
    unsigned bm; int c, off, S;
#define SCAN_FLAGS(T)                                                      \
    {                                                                      \
        bm = 0u;                                                           \
        _Pragma("unroll")                                                  \
        for (int j = 0; j < 8; j++) bm |= (v[j] >= (T)) ? (1u << j) : 0u;  \
        c = __popc(bm);                                                    \
        off = c;                                                           \
        _Pragma("unroll")                                                  \
        for (int d = 1; d < 32; d <<= 1) {                                 \
            int t_ = __shfl_up_sync(FULL, off, d);                         \
            if (lane >= d) off += t_;                                      \
        }                                                                  \
        S = __shfl_sync(FULL, off, 31);                                    \
        off -= c;                                                          \
    }
    SCAN_FLAGS(thr);

    // Rare fallback: m8 = exact 8th-largest of the 32 lane maxima. Only the 8
    // lanes whose max >= m8 can contribute, each <= 8 elements => S <= 64 PROVEN.
    if (S > 64) {
        float s = lm;
#pragma unroll
        for (int k = 2; k <= 32; k <<= 1) {
#pragma unroll
            for (int j = k >> 1; j > 0; j >>= 1) {
                float o_ = __shfl_xor_sync(FULL, s, j);
                bool up    = ((lane & k) == 0);
                bool lower = ((lane & j) == 0);
                s = (lower == up) ? fminf(s, o_) : fmaxf(s, o_);
            }
        }
        float m8f = __shfl_sync(FULL, s, 24);   // ascending: 8th largest at lane 24
        SCAN_FLAGS(m8f);
    }
#undef SCAN_FLAGS
    // Invariants: 8 <= S <= 64.

    // ---- Compact survivors as packed u64; pad disjoint slots; ONE syncwarp ----
    unsigned long long* K = sk[wib];
    const int base = lane * 4;
#pragma unroll
    for (int j = 0; j < 8; j++) {
        if (bm & (1u << j)) {
            int g = (j < 4) ? (base + j) : (124 + base + j);   // 128 + base + (j-4)
            K[off] = ((unsigned long long)__float_as_uint(v[j]) << 32) | (unsigned)g;
            off++;
        }
    }
    if (lane >= S) K[lane] = PAD;                       // pads [S,32) (fast path reads 0..31)
    if (S > 32) {                                       // rare: pads [max(S,32),64) + tail
        if (lane + 32 >= S) K[lane + 32] = PAD;
        if (lane < 4) K[64 + lane] = PAD;               // loop over-read up to S+3 <= 67
    }
    __syncwarp();

    // Candidate = slot `lane` (exact value + index from one LDS.64).
    unsigned long long k1 = K[lane];
    float c1v = __uint_as_float((unsigned)(k1 >> 32));
    int   c1g = (int)(unsigned)k1;

    int r1 = 99, r2 = 99;
    if (S <= 32) {
        // ---- fp16x2 SIMD ranking (common ~97%) ----
        __half2* SH = sh[wib];
        if (lane < 16) {
            uint4 t = reinterpret_cast<const uint4*>(K)[lane];  // slots 2*lane, 2*lane+1
            SH[lane] = __floats2half2_rn(__uint_as_float(t.y), __uint_as_float(t.w));
        }
        __syncwarp();
        __half2 c2 = __half2half2(__float2half_rn(c1v));  // same rn conversion as array
        const uint4* q = reinterpret_cast<const uint4*>(SH);
        uint4 q0 = q[0], q1 = q[1], q2 = q[2], q3 = q[3];
        unsigned u[16] = {q0.x,q0.y,q0.z,q0.w, q1.x,q1.y,q1.z,q1.w,
                          q2.x,q2.y,q2.z,q2.w, q3.x,q3.y,q3.z,q3.w};
        __half2 acc0 = __float2half2_rn(0.f), acc1 = __float2half2_rn(0.f);
#pragma unroll
        for (int i = 0; i < 16; i += 2) {
            __half2 e0 = *reinterpret_cast<const __half2*>(&u[i]);
            __half2 e1 = *reinterpret_cast<const __half2*>(&u[i + 1]);
            acc0 = __hadd2(acc0, __hgt2(e0, c2));
            acc1 = __hadd2(acc1, __hgt2(e1, c2));
        }
        __half2 acc = __hadd2(acc0, acc1);
        r1 = (int)(__low2float(acc) + __high2float(acc));
    } else {
        // ---- Rare: up to 64 survivors, exact f32 ranking, 2 candidates/lane ----
        unsigned long long k2 = K[lane + 32];
        float c2v = __uint_as_float((unsigned)(k2 >> 32));
        int ra = 0, rb = 0;
        const uint4* Kq = reinterpret_cast<const uint4*>(K);   // 2 slots per uint4
        const int nI = (S + 1) >> 1;
        for (int i = 0; i < nI; i++) {
            uint4 t = Kq[i];
            float va = __uint_as_float(t.y), vb = __uint_as_float(t.w);
            ra += (va > c1v) + (vb > c1v);
            rb += (va > c2v) + (vb > c2v);
        }
        r1 = ra;
        r2 = rb;
    }

    // ---- Exactness check: winners must cover ranks 0..7 exactly once.
    // Any fp16 collision or f32 tie that could corrupt the top-8 breaks this.
    unsigned wbit = ((r1 < 8) ? (1u << r1) : 0u) | ((r2 < 8) ? (1u << r2) : 0u);
    unsigned cnt  = (unsigned)(r1 < 8) + (unsigned)(r2 < 8);
    unsigned mask = __reduce_or_sync(FULL, wbit);
    unsigned tot  = __reduce_add_sync(FULL, cnt);
    if (!(mask == 0xFFu && tot == 8u)) {
        // Exact tie-aware ranking (value desc, index asc) — matches jax.lax.top_k.
        float c2v = NEG_INF; int c2g = 0;
        if (S > 32) {
            unsigned long long k2 = K[lane + 32];
            c2v = __uint_as_float((unsigned)(k2 >> 32));
            c2g = (int)(unsigned)k2;
        }
        int ra = 0, rb = 0;
        for (int i = 0; i < S; i++) {
            unsigned long long k = K[i];
            float ev = __uint_as_float((unsigned)(k >> 32));
            int   eg = (int)(unsigned)k;
            ra += (ev > c1v) || (ev == c1v && eg < c1g);
            rb += (ev > c2v) || (ev == c2v && eg < c2g);
        }
        r1 = ra;
        r2 = (S > 32) ? rb : 99;
    }

    // ---- Winners write their slot directly ----
    // Layout: [weights (TOKENS*8) | indices-as-float (TOKENS*8)]
    float* wbase = out + (size_t)warp * TOPK;
    float* ibase = out + (size_t)NUM_TOKENS * TOPK + (size_t)warp * TOPK;
    if (r1 < 8) {
        wbase[r1] = ex2(fmaf(c1v, LOG2E, woff));
        ibase[r1] = (float)c1g;
    }
    if (r2 < 8) {
        unsigned long long k2 = K[lane + 32];
        float c2v = __uint_as_float((unsigned)(k2 >> 32));
        int   c2g = (int)(unsigned)k2;
        wbase[r2] = ex2(fmaf(c2v, LOG2E, woff));
        ibase[r2] = (float)c2g;
    }
}

extern "C" void kernel_launch(void* const* d_in, const int* in_sizes, int n_in,
                              void* d_out, int out_size) {
    const float* gating = (const float*)d_in[0];
    float* out = (float*)d_out;
    const int blocks = NUM_TOKENS / 8;   // 8 warps (tokens) per 256-thread block
    moe_topk_softmax_kernel<<<blocks, 256>>>(gating, out);
}

// round 16
// speedup vs baseline: 1.0149x; 1.0149x over previous
#include <cuda_runtime.h>
#include <cuda_fp16.h>
#include <cstdint>

#define NUM_TOKENS 131072
#define NUM_EXPERTS 256
#define TOPK 8
#define LOG2E 1.4426950408889634f

__device__ __forceinline__ float ex2(float x) {
    float y; asm("ex2.approx.ftz.f32 %0, %1;" : "=f"(y) : "f"(x)); return y;
}
__device__ __forceinline__ float lg2(float x) {
    float y; asm("lg2.approx.ftz.f32 %0, %1;" : "=f"(y) : "f"(x)); return y;
}

__global__ void __launch_bounds__(256, 8)
moe_topk_softmax_kernel(const float* __restrict__ gating,
                        float* __restrict__ out) {
    __shared__ __align__(16) float   sv[8][72];  // f32 survivor values (+pad region)
    __shared__ __align__(16) int     si[8][64];  // survivor expert indices
    __shared__ __align__(16) __half2 sh[8][16];  // fp16-packed survivors, slots 0..31
    const unsigned FULL = 0xffffffffu;
    const int wib  = threadIdx.x >> 5;
    const int lane = threadIdx.x & 31;
    const int warp = blockIdx.x * 8 + wib;
    const float NEG_INF = __int_as_float(0xff800000);

    // Coalesced row load: 64 float4 per row
    const float4* row = reinterpret_cast<const float4*>(gating + (size_t)warp * NUM_EXPERTS);
    float4 A = __ldg(&row[lane]);
    float4 B = __ldg(&row[lane + 32]);
    float v[8] = {A.x, A.y, A.z, A.w, B.x, B.y, B.z, B.w};

    // Per-lane max
    float lm = v[0];
#pragma unroll
    for (int j = 1; j < 8; j++) lm = fmaxf(lm, v[j]);

    // thr = min of the 8 quad maxima (8 disjoint 32-elem groups => thr <= t8, and
    // all 8 quad maxima >= thr => S >= 8). rmax = row max.
    float qm = fmaxf(lm, __shfl_xor_sync(FULL, lm, 1));
    qm = fmaxf(qm, __shfl_xor_sync(FULL, qm, 2));
    float thr = qm, rmax = qm;
#pragma unroll
    for (int o = 4; o < 32; o <<= 1) {
        thr  = fminf(thr,  __shfl_xor_sync(FULL, thr,  o));
        rmax = fmaxf(rmax, __shfl_xor_sync(FULL, rmax, o));
    }

    // ---- Softmax denominator early; fold into exponent offset ----
    const float rm2 = rmax * LOG2E;
    float sm = 0.f;
#pragma unroll
    for (int j = 0; j < 8; j++) sm += ex2(fmaf(v[j], LOG2E, -rm2));
#pragma unroll
    for (int o = 1; o < 32; o <<= 1) sm += __shfl_xor_sync(FULL, sm, o);
    const float woff = -rm2 - lg2(sm);   // weight = ex2(fma(v, LOG2E, woff))

    // ---- Flag mask + exclusive prefix scan of survivor counts ----
    unsigned bm; int c, off, S;
#define SCAN_FLAGS(T)                                                      \
    {                                                                      \
        bm = 0u;                                                           \
        _Pragma("unroll")                                                  \
        for (int j = 0; j < 8; j++) bm |= (v[j] >= (T)) ? (1u << j) : 0u;  \
        c = __popc(bm);                                                    \
        off = c;                                                           \
        _Pragma("unroll")                                                  \
        for (int d = 1; d < 32; d <<= 1) {                                 \
            int t_ = __shfl_up_sync(FULL, off, d);                         \
            if (lane >= d) off += t_;                                      \
        }                                                                  \
        S = __shfl_sync(FULL, off, 31);                                    \
        off -= c;                                                          \
    }
    SCAN_FLAGS(thr);

    // Rare fallback: m8 = exact 8th-largest of the 32 lane maxima. Only the 8
    // lanes whose max >= m8 can contribute, each <= 8 elements => S <= 64 PROVEN.
    if (S > 64) {
        float s = lm;
#pragma unroll
        for (int k = 2; k <= 32; k <<= 1) {
#pragma unroll
            for (int j = k >> 1; j > 0; j >>= 1) {
                float o_ = __shfl_xor_sync(FULL, s, j);
                bool up    = ((lane & k) == 0);
                bool lower = ((lane & j) == 0);
                s = (lower == up) ? fminf(s, o_) : fmaxf(s, o_);
            }
        }
        float m8f = __shfl_sync(FULL, s, 24);   // ascending: 8th largest at lane 24
        SCAN_FLAGS(m8f);
    }
#undef SCAN_FLAGS
    // Invariants: 8 <= S <= 64 (no clamp, no per-store guard needed).

    float* WV = sv[wib];
    int*   WI = si[wib];
    WV[lane] = NEG_INF;                       // pad slots 0..31
    if (S > 32) WV[lane + 32] = NEG_INF;      // pad slots 32..63 (rare, warp-uniform)
    __syncwarp();

    // ---- Compact survivors (value + index); off < S <= 64 always in-bounds ----
    const int base = lane * 4;
#pragma unroll
    for (int j = 0; j < 8; j++) {
        if (bm & (1u << j)) {
            int g = (j < 4) ? (base + j) : (124 + base + j);   // 128 + base + (j-4)
            WV[off] = v[j]; WI[off] = g;
            off++;
        }
    }
    __syncwarp();

    int r1 = 99, r2 = 99;
    if (S <= 32) {
        // ---- fp16x2 SIMD ranking (common ~97%) ----
        // Convert slots 0..31 (real + -inf pad) to packed half2.
        __half2* SH = sh[wib];
        if (lane < 16) {
            float2 fp = reinterpret_cast<const float2*>(WV)[lane];
            SH[lane] = __floats2half2_rn(fp.x, fp.y);   // .x -> low = slot 2*lane
        }
        __syncwarp();
        // Candidate = slot `lane` (fp16). Pad candidates (-inf) self-rank >= S >= 8.
        __half  ch = reinterpret_cast<const __half*>(SH)[lane];
        __half2 c2 = __half2half2(ch);
        const uint4* q = reinterpret_cast<const uint4*>(SH);
        uint4 q0 = q[0], q1 = q[1], q2 = q[2], q3 = q[3];
        unsigned u[16] = {q0.x,q0.y,q0.z,q0.w, q1.x,q1.y,q1.z,q1.w,
                          q2.x,q2.y,q2.z,q2.w, q3.x,q3.y,q3.z,q3.w};
        __half2 acc0 = __float2half2_rn(0.f), acc1 = __float2half2_rn(0.f);
#pragma unroll
        for (int i = 0; i < 16; i += 2) {
            __half2 e0 = *reinterpret_cast<const __half2*>(&u[i]);
            __half2 e1 = *reinterpret_cast<const __half2*>(&u[i + 1]);
            acc0 = __hadd2(acc0, __hgt2(e0, c2));
            acc1 = __hadd2(acc1, __hgt2(e1, c2));
        }
        __half2 acc = __hadd2(acc0, acc1);
        r1 = (int)(__low2float(acc) + __high2float(acc));
    } else {
        // ---- Rare: up to 64 survivors, exact f32 ranking, 2 candidates/lane ----
        float c1v = WV[lane], c2v = WV[lane + 32];
        int ra = 0, rb = 0;
        const float4* WV4 = reinterpret_cast<const float4*>(WV);
        const int nIter = (S + 3) >> 2;
        for (int i = 0; i < nIter; i++) {
            float4 e = WV4[i];
            ra += (e.x > c1v) + (e.y > c1v) + (e.z > c1v) + (e.w > c1v);
            rb += (e.x > c2v) + (e.y > c2v) + (e.z > c2v) + (e.w > c2v);
        }
        r1 = ra;
        r2 = rb;
    }

    // ---- Exactness check: winners must cover ranks 0..7 exactly once.
    // Any fp16 collision or f32 tie that could corrupt the top-8 breaks this.
    unsigned wbit = ((r1 < 8) ? (1u << r1) : 0u) | ((r2 < 8) ? (1u << r2) : 0u);
    unsigned cnt  = (unsigned)(r1 < 8) + (unsigned)(r2 < 8);
    unsigned mask = __reduce_or_sync(FULL, wbit);
    unsigned tot  = __reduce_add_sync(FULL, cnt);
    if (!(mask == 0xFFu && tot == 8u)) {
        // Exact tie-aware ranking (value desc, index asc) — matches jax.lax.top_k.
        float c1v = WV[lane];
        int   c1g = WI[lane];
        float c2v = (S > 32) ? WV[lane + 32] : NEG_INF;
        int   c2g = (S > 32) ? WI[lane + 32] : 0;
        int ra = 0, rb = 0;
        for (int i = 0; i < S; i++) {
            float ev = WV[i]; int eg = WI[i];
            ra += (ev > c1v) || (ev == c1v && eg < c1g);
            rb += (ev > c2v) || (ev == c2v && eg < c2g);
        }
        r1 = ra;
        r2 = (S > 32) ? rb : 99;
    }

    // ---- Winners write their slot directly ----
    // Layout: [weights (TOKENS*8) | indices-as-float (TOKENS*8)]
    float* wbase = out + (size_t)warp * TOPK;
    float* ibase = out + (size_t)NUM_TOKENS * TOPK + (size_t)warp * TOPK;
    if (r1 < 8) {
        wbase[r1] = ex2(fmaf(WV[lane], LOG2E, woff));
        ibase[r1] = (float)WI[lane];
    }
    if (r2 < 8) {
        wbase[r2] = ex2(fmaf(WV[lane + 32], LOG2E, woff));
        ibase[r2] = (float)WI[lane + 32];
    }
}

extern "C" void kernel_launch(void* const* d_in, const int* in_sizes, int n_in,
                              void* d_out, int out_size) {
    const float* gating = (const float*)d_in[0];
    float* out = (float*)d_out;
    const int blocks = NUM_TOKENS / 8;   // 8 warps (tokens) per 256-thread block
    moe_topk_softmax_kernel<<<blocks, 256>>>(gating, out);
}